// round 2
// baseline (speedup 1.0000x reference)
#include <cuda_runtime.h>
#include <math.h>

#define NF 128
#define NB 64
#define NODES1 131072
#define EMAX 2097152

// ---------------- scratch (static device globals; no allocation) ----------------
__device__ float g_h[NODES1 * NF];      // ping
__device__ float g_h2[NODES1 * NF];     // pong
__device__ float g_mean[NODES1 * NF];   // aggregated means
__device__ int   g_esrc[EMAX];
__device__ int   g_edst[EMAX];
__device__ int   g_esrc2[EMAX];
__device__ int   g_edst2[EMAX];
__device__ int   g_csr[EMAX];
__device__ int   g_deg[NODES1];
__device__ int   g_rows[NODES1];
__device__ int   g_curs[NODES1];
__device__ int   g_kept[NODES1];
__device__ int   g_newidx[NODES1];
__device__ float g_score[NODES1];
__device__ float g_z[NB * 256];
__device__ int   g_cnt[4];              // [0]=E (layer1), [1]=compacted1, [2]=compacted2

// ---------------- small utility kernels ----------------
__global__ void k_init() { g_cnt[0] = EMAX; g_cnt[1] = 0; g_cnt[2] = 0; }

__global__ void k_zero_i(int* p, int n) {
    int i = blockIdx.x * blockDim.x + threadIdx.x;
    if (i < n) p[i] = 0;
}
__global__ void k_zero_f(float* p, int n) {
    int i = blockIdx.x * blockDim.x + threadIdx.x;
    if (i < n) p[i] = 0.f;
}

// ---------------- CSR build ----------------
__global__ void k_hist(const int* __restrict__ dst, const int* __restrict__ pcnt,
                       int* __restrict__ deg) {
    int En = *pcnt;
    int stride = gridDim.x * blockDim.x;
    for (int e = blockIdx.x * blockDim.x + threadIdx.x; e < En; e += stride)
        atomicAdd(&deg[dst[e]], 1);
}

__global__ void k_scatter(const int* __restrict__ src, const int* __restrict__ dst,
                          const int* __restrict__ pcnt, const int* __restrict__ rows,
                          int* __restrict__ curs, int* __restrict__ csr) {
    int En = *pcnt;
    int stride = gridDim.x * blockDim.x;
    for (int e = blockIdx.x * blockDim.x + threadIdx.x; e < En; e += stride) {
        int d = dst[e];
        int p = atomicAdd(&curs[d], 1);
        csr[rows[d] + p] = src[e];
    }
}

// single-block exclusive scan; n must be a multiple of 8192 (131072/65536/32768 all are)
__global__ void k_scan(const int* __restrict__ in, int* __restrict__ out, int n) {
    __shared__ int swarp[32];
    __shared__ int scarry;
    int tid = threadIdx.x, lane = tid & 31, w = tid >> 5;
    if (tid == 0) scarry = 0;
    __syncthreads();
    for (int base = 0; base < n; base += 8192) {
        int idx = base + tid * 8;
        int4 a = *(const int4*)(in + idx);
        int4 b = *(const int4*)(in + idx + 4);
        int p0 = 0;
        int p1 = p0 + a.x, p2 = p1 + a.y, p3 = p2 + a.z, p4 = p3 + a.w;
        int p5 = p4 + b.x, p6 = p5 + b.y, p7 = p6 + b.z;
        int s = p7 + b.w;
        int incl = s;
        #pragma unroll
        for (int o = 1; o < 32; o <<= 1) {
            int t = __shfl_up_sync(0xffffffffu, incl, o);
            if (lane >= o) incl += t;
        }
        if (lane == 31) swarp[w] = incl;
        __syncthreads();
        if (w == 0) {
            int ws = swarp[lane];
            int wincl = ws;
            #pragma unroll
            for (int o = 1; o < 32; o <<= 1) {
                int t = __shfl_up_sync(0xffffffffu, wincl, o);
                if (lane >= o) wincl += t;
            }
            swarp[lane] = wincl - ws;
        }
        __syncthreads();
        int off = scarry + swarp[w] + (incl - s);
        int4 o1; o1.x = off + p0; o1.y = off + p1; o1.z = off + p2; o1.w = off + p3;
        int4 o2; o2.x = off + p4; o2.y = off + p5; o2.z = off + p6; o2.w = off + p7;
        *(int4*)(out + idx) = o1;
        *(int4*)(out + idx + 4) = o2;
        __syncthreads();
        if (tid == 1023) scarry = off + s;
        __syncthreads();
    }
}

// ---------------- neighbor mean aggregation: one warp per node ----------------
__global__ void k_aggregate(const float* __restrict__ x, const int* __restrict__ rows,
                            const int* __restrict__ csr, const int* __restrict__ deg,
                            float* __restrict__ mb) {
    int node = blockIdx.x * 8 + (threadIdx.x >> 5);
    int lane = threadIdx.x & 31;
    int r0 = rows[node];
    int d = deg[node];
    float ax = 0.f, ay = 0.f, az = 0.f, aw = 0.f;
    int j = 0;
    for (; j + 4 <= d; j += 4) {
        int s0 = csr[r0 + j], s1 = csr[r0 + j + 1], s2 = csr[r0 + j + 2], s3 = csr[r0 + j + 3];
        float4 v0 = *(const float4*)(x + (size_t)s0 * NF + lane * 4);
        float4 v1 = *(const float4*)(x + (size_t)s1 * NF + lane * 4);
        float4 v2 = *(const float4*)(x + (size_t)s2 * NF + lane * 4);
        float4 v3 = *(const float4*)(x + (size_t)s3 * NF + lane * 4);
        ax += v0.x + v1.x + v2.x + v3.x;
        ay += v0.y + v1.y + v2.y + v3.y;
        az += v0.z + v1.z + v2.z + v3.z;
        aw += v0.w + v1.w + v2.w + v3.w;
    }
    for (; j < d; j++) {
        int s = csr[r0 + j];
        float4 v = *(const float4*)(x + (size_t)s * NF + lane * 4);
        ax += v.x; ay += v.y; az += v.z; aw += v.w;
    }
    float inv = 1.f / (float)(d > 0 ? d : 1);
    float4 o; o.x = ax * inv; o.y = ay * inv; o.z = az * inv; o.w = aw * inv;
    *(float4*)(mb + (size_t)node * NF + lane * 4) = o;
}

// ---------------- out = relu(A@Wl + X@Wr + b), A,X: [M,128], W: [128,128] ----------------
__global__ void __launch_bounds__(256) k_gemm(
    const float* __restrict__ A, const float* __restrict__ X,
    const float* __restrict__ Wl, const float* __restrict__ Wr,
    const float* __restrict__ bias, float* __restrict__ out) {
    __shared__ __align__(16) float As[8][128];
    __shared__ __align__(16) float Bs[8][132];
    int tid = threadIdx.x;
    int r0 = blockIdx.x * 128;
    int tx = tid & 15, ty = tid >> 4;
    int lm = tid >> 1, lk4 = (tid & 1) * 4;
    int bk = tid >> 5, bn = (tid & 31) * 4;
    float c[8][8];
    #pragma unroll
    for (int i = 0; i < 8; i++)
        #pragma unroll
        for (int j = 0; j < 8; j++) c[i][j] = 0.f;

    #pragma unroll
    for (int p = 0; p < 2; p++) {
        const float* S = p ? X : A;
        const float* W = p ? Wr : Wl;
        for (int kb = 0; kb < 128; kb += 8) {
            float4 av = *(const float4*)(S + (size_t)(r0 + lm) * 128 + kb + lk4);
            float4 bv = *(const float4*)(W + (size_t)(kb + bk) * 128 + bn);
            __syncthreads();
            As[lk4 + 0][lm] = av.x;
            As[lk4 + 1][lm] = av.y;
            As[lk4 + 2][lm] = av.z;
            As[lk4 + 3][lm] = av.w;
            *(float4*)&Bs[bk][bn] = bv;
            __syncthreads();
            #pragma unroll
            for (int k = 0; k < 8; k++) {
                float a[8], b[8];
                *(float4*)(a)     = *(const float4*)&As[k][ty * 8];
                *(float4*)(a + 4) = *(const float4*)&As[k][ty * 8 + 4];
                *(float4*)(b)     = *(const float4*)&Bs[k][tx * 8];
                *(float4*)(b + 4) = *(const float4*)&Bs[k][tx * 8 + 4];
                #pragma unroll
                for (int i = 0; i < 8; i++)
                    #pragma unroll
                    for (int j = 0; j < 8; j++) c[i][j] += a[i] * b[j];
            }
        }
    }
    float bb[8];
    #pragma unroll
    for (int j = 0; j < 8; j++) bb[j] = bias[tx * 8 + j];
    #pragma unroll
    for (int i = 0; i < 8; i++) {
        size_t row = (size_t)(r0 + ty * 8 + i);
        float4 o1, o2;
        o1.x = fmaxf(c[i][0] + bb[0], 0.f);
        o1.y = fmaxf(c[i][1] + bb[1], 0.f);
        o1.z = fmaxf(c[i][2] + bb[2], 0.f);
        o1.w = fmaxf(c[i][3] + bb[3], 0.f);
        o2.x = fmaxf(c[i][4] + bb[4], 0.f);
        o2.y = fmaxf(c[i][5] + bb[5], 0.f);
        o2.z = fmaxf(c[i][6] + bb[6], 0.f);
        o2.w = fmaxf(c[i][7] + bb[7], 0.f);
        *(float4*)(out + row * 128 + tx * 8)     = o1;
        *(float4*)(out + row * 128 + tx * 8 + 4) = o2;
    }
}

// ---------------- score = tanh(h·w / ||w||), one warp per node ----------------
__global__ void k_score(const float* __restrict__ h, const float* __restrict__ pw,
                        float* __restrict__ score) {
    __shared__ __align__(16) float spw[128];
    __shared__ float sinv;
    int tid = threadIdx.x;
    if (tid < 128) spw[tid] = pw[tid];
    __syncthreads();
    if (tid == 0) {
        float s = 0.f;
        for (int i = 0; i < 128; i++) s += spw[i] * spw[i];
        sinv = 1.0f / sqrtf(s);
    }
    __syncthreads();
    int node = blockIdx.x * 8 + (tid >> 5);
    int lane = tid & 31;
    float4 v = *(const float4*)(h + (size_t)node * 128 + lane * 4);
    float4 w = *(const float4*)(&spw[lane * 4]);
    float d = v.x * w.x + v.y * w.y + v.z * w.z + v.w * w.w;
    #pragma unroll
    for (int o = 16; o > 0; o >>= 1) d += __shfl_down_sync(0xffffffffu, d, o);
    if (lane == 0) score[node] = tanhf(d * sinv);
}

// ---------------- per-graph top-k pool (bitonic sort, reference tie-break) ----------------
__global__ void k_pool(const float* __restrict__ h, const float* __restrict__ score,
                       float* __restrict__ hout, int* __restrict__ kept,
                       int* __restrict__ newidx, int n_per, int k) {
    __shared__ unsigned long long s_key[2048];
    int g = blockIdx.x;
    int tid = threadIdx.x;
    int bd = blockDim.x;
    int base = g * n_per;
    for (int i = tid; i < n_per; i += bd) {
        float s = score[base + i];
        unsigned u = __float_as_uint(s);
        unsigned au = (u & 0x80000000u) ? ~u : (u | 0x80000000u);  // ascending float order
        unsigned du = ~au;                                          // descending
        s_key[i] = ((unsigned long long)du << 32) | (unsigned)i;
        kept[base + i] = 0;
    }
    for (int size = 2; size <= n_per; size <<= 1) {
        for (int stride = size >> 1; stride > 0; stride >>= 1) {
            __syncthreads();
            int half = n_per >> 1;
            for (int t = tid; t < half; t += bd) {
                int i = 2 * t - (t & (stride - 1));
                int j = i + stride;
                unsigned long long a = s_key[i], c = s_key[j];
                bool up = ((i & size) == 0);
                if ((a > c) == up) { s_key[i] = c; s_key[j] = a; }
            }
        }
    }
    __syncthreads();
    for (int t = tid; t < k; t += bd) {
        int li = (int)(s_key[t] & 0xffffffffull);
        kept[base + li] = 1;
        newidx[base + li] = g * k + t;  // reference perm ordering (score-desc)
    }
    int w = tid >> 5, lane = tid & 31, nw = bd >> 5;
    for (int t = w; t < k; t += nw) {
        int li = (int)(s_key[t] & 0xffffffffull);
        int v = base + li;
        float sc = score[v];
        float4 val = *(const float4*)(h + (size_t)v * NF + lane * 4);
        float4 o; o.x = val.x * sc; o.y = val.y * sc; o.z = val.z * sc; o.w = val.w * sc;
        *(float4*)(hout + (size_t)(g * k + t) * NF + lane * 4) = o;
    }
}

// ---------------- drop masked edges + relabel (warp-aggregated compaction) ----------------
__global__ void k_compact(const int* __restrict__ src, const int* __restrict__ dst,
                          const int* __restrict__ pcnt, const int* __restrict__ kept,
                          const int* __restrict__ newidx,
                          int* __restrict__ osrc, int* __restrict__ odst,
                          int* __restrict__ ocnt) {
    int En = *pcnt;
    int lane = threadIdx.x & 31;
    int stride = gridDim.x * blockDim.x;
    int base = blockIdx.x * blockDim.x + (threadIdx.x & ~31);
    for (int b = base; b < En; b += stride) {
        int e = b + lane;
        bool keep = false;
        int ns = 0, nd = 0;
        if (e < En) {
            int s = src[e], d2 = dst[e];
            if (kept[s] && kept[d2]) { keep = true; ns = newidx[s]; nd = newidx[d2]; }
        }
        unsigned m = __ballot_sync(0xffffffffu, keep);
        int cnt = __popc(m);
        int pos = 0;
        if (lane == 0 && cnt) pos = atomicAdd(ocnt, cnt);
        pos = __shfl_sync(0xffffffffu, pos, 0);
        if (keep) {
            int off = __popc(m & ((1u << lane) - 1u));
            osrc[pos + off] = ns;
            odst[pos + off] = nd;
        }
    }
}

// ---------------- readout: z[g] += [max, mean] over graph rows ----------------
__global__ void k_readout(const float* __restrict__ h, float* __restrict__ z, int n_per) {
    __shared__ float smx[8][128];
    __shared__ float ssm[8][128];
    int g = blockIdx.x;
    int tid = threadIdx.x;
    int f = tid & 127, grp = tid >> 7;
    float mx = -3.402823466e38f, sm = 0.f;
    for (int r = grp; r < n_per; r += 8) {
        float v = h[(size_t)(g * n_per + r) * NF + f];
        mx = fmaxf(mx, v);
        sm += v;
    }
    smx[grp][f] = mx;
    ssm[grp][f] = sm;
    __syncthreads();
    if (grp == 0) {
        for (int j = 1; j < 8; j++) { mx = fmaxf(mx, smx[j][f]); sm += ssm[j][f]; }
        z[g * 256 + f] += mx;
        z[g * 256 + 128 + f] += sm / (float)n_per;
    }
}

// ---------------- final MLP + log_softmax ----------------
__global__ void k_mlp(const float* __restrict__ z,
                      const float* __restrict__ w1, const float* __restrict__ b1,
                      const float* __restrict__ w2, const float* __restrict__ b2,
                      const float* __restrict__ w3, const float* __restrict__ b3,
                      float* __restrict__ out) {
    __shared__ float zin[256];
    __shared__ float h1[128];
    __shared__ float h2[64];
    __shared__ float z2[2];
    int g = blockIdx.x, tid = threadIdx.x;
    zin[tid] = z[g * 256 + tid];
    zin[tid + 128] = z[g * 256 + 128 + tid];
    __syncthreads();
    float a = b1[tid];
    for (int k2 = 0; k2 < 256; k2++) a += zin[k2] * w1[k2 * 128 + tid];
    h1[tid] = fmaxf(a, 0.f);
    __syncthreads();
    if (tid < 64) {
        float a2 = b2[tid];
        for (int k2 = 0; k2 < 128; k2++) a2 += h1[k2] * w2[k2 * 64 + tid];
        h2[tid] = fmaxf(a2, 0.f);
    }
    __syncthreads();
    if (tid < 2) {
        float a3 = b3[tid];
        for (int k2 = 0; k2 < 64; k2++) a3 += h2[k2] * w3[k2 * 2 + tid];
        z2[tid] = a3;
    }
    __syncthreads();
    if (tid < 2) {
        float m = fmaxf(z2[0], z2[1]);
        float lse = m + logf(expf(z2[0] - m) + expf(z2[1] - m));
        out[g * 2 + tid] = z2[tid] - lse;
    }
}

// ---------------- host ----------------
extern "C" void kernel_launch(void* const* d_in, const int* in_sizes, int n_in,
                              void* d_out, int out_size) {
    const float* x   = (const float*)d_in[0];
    const int*   src = (const int*)d_in[1];
    const int*   dst = (const int*)d_in[2];
    const float* w1l = (const float*)d_in[3];
    const float* b1  = (const float*)d_in[4];
    const float* w1r = (const float*)d_in[5];
    const float* pw1 = (const float*)d_in[6];
    const float* w2l = (const float*)d_in[7];
    const float* b2  = (const float*)d_in[8];
    const float* w2r = (const float*)d_in[9];
    const float* pw2 = (const float*)d_in[10];
    const float* w3l = (const float*)d_in[11];
    const float* b3  = (const float*)d_in[12];
    const float* w3r = (const float*)d_in[13];
    const float* pw3 = (const float*)d_in[14];
    const float* l1w = (const float*)d_in[15];
    const float* l1b = (const float*)d_in[16];
    const float* l2w = (const float*)d_in[17];
    const float* l2b = (const float*)d_in[18];
    const float* l3w = (const float*)d_in[19];
    const float* l3b = (const float*)d_in[20];
    float* out = (float*)d_out;

    float *p_h, *p_h2, *p_mean, *p_score, *p_z;
    int *p_esrc, *p_edst, *p_esrc2, *p_edst2, *p_csr, *p_deg, *p_rows, *p_curs,
        *p_kept, *p_newidx, *p_cnt;
    cudaGetSymbolAddress((void**)&p_h, g_h);
    cudaGetSymbolAddress((void**)&p_h2, g_h2);
    cudaGetSymbolAddress((void**)&p_mean, g_mean);
    cudaGetSymbolAddress((void**)&p_score, g_score);
    cudaGetSymbolAddress((void**)&p_z, g_z);
    cudaGetSymbolAddress((void**)&p_esrc, g_esrc);
    cudaGetSymbolAddress((void**)&p_edst, g_edst);
    cudaGetSymbolAddress((void**)&p_esrc2, g_esrc2);
    cudaGetSymbolAddress((void**)&p_edst2, g_edst2);
    cudaGetSymbolAddress((void**)&p_csr, g_csr);
    cudaGetSymbolAddress((void**)&p_deg, g_deg);
    cudaGetSymbolAddress((void**)&p_rows, g_rows);
    cudaGetSymbolAddress((void**)&p_curs, g_curs);
    cudaGetSymbolAddress((void**)&p_kept, g_kept);
    cudaGetSymbolAddress((void**)&p_newidx, g_newidx);
    cudaGetSymbolAddress((void**)&p_cnt, g_cnt);

    k_init<<<1, 1>>>();
    k_zero_f<<<(NB * 256 + 255) / 256, 256>>>(p_z, NB * 256);

    // ===== layer 1 : 131072 nodes, full edge list =====
    k_zero_i<<<(131072 + 255) / 256, 256>>>(p_deg, 131072);
    k_zero_i<<<(131072 + 255) / 256, 256>>>(p_curs, 131072);
    k_hist<<<2048, 256>>>(dst, p_cnt + 0, p_deg);
    k_scan<<<1, 1024>>>(p_deg, p_rows, 131072);
    k_scatter<<<2048, 256>>>(src, dst, p_cnt + 0, p_rows, p_curs, p_csr);
    k_aggregate<<<131072 / 8, 256>>>(x, p_rows, p_csr, p_deg, p_mean);
    k_gemm<<<131072 / 128, 256>>>(p_mean, x, w1l, w1r, b1, p_h2);
    k_score<<<131072 / 8, 256>>>(p_h2, pw1, p_score);
    k_pool<<<64, 1024>>>(p_h2, p_score, p_h, p_kept, p_newidx, 2048, 1024);
    k_compact<<<2048, 256>>>(src, dst, p_cnt + 0, p_kept, p_newidx, p_esrc, p_edst, p_cnt + 1);
    k_readout<<<64, 1024>>>(p_h, p_z, 1024);

    // ===== layer 2 : 65536 nodes, compacted edges =====
    k_zero_i<<<(65536 + 255) / 256, 256>>>(p_deg, 65536);
    k_zero_i<<<(65536 + 255) / 256, 256>>>(p_curs, 65536);
    k_hist<<<2048, 256>>>(p_edst, p_cnt + 1, p_deg);
    k_scan<<<1, 1024>>>(p_deg, p_rows, 65536);
    k_scatter<<<2048, 256>>>(p_esrc, p_edst, p_cnt + 1, p_rows, p_curs, p_csr);
    k_aggregate<<<65536 / 8, 256>>>(p_h, p_rows, p_csr, p_deg, p_mean);
    k_gemm<<<65536 / 128, 256>>>(p_mean, p_h, w2l, w2r, b2, p_h2);
    k_score<<<65536 / 8, 256>>>(p_h2, pw2, p_score);
    k_pool<<<64, 1024>>>(p_h2, p_score, p_h, p_kept, p_newidx, 1024, 512);
    k_compact<<<2048, 256>>>(p_esrc, p_edst, p_cnt + 1, p_kept, p_newidx, p_esrc2, p_edst2, p_cnt + 2);
    k_readout<<<64, 1024>>>(p_h, p_z, 512);

    // ===== layer 3 : 32768 nodes =====
    k_zero_i<<<(32768 + 255) / 256, 256>>>(p_deg, 32768);
    k_zero_i<<<(32768 + 255) / 256, 256>>>(p_curs, 32768);
    k_hist<<<2048, 256>>>(p_edst2, p_cnt + 2, p_deg);
    k_scan<<<1, 1024>>>(p_deg, p_rows, 32768);
    k_scatter<<<2048, 256>>>(p_esrc2, p_edst2, p_cnt + 2, p_rows, p_curs, p_csr);
    k_aggregate<<<32768 / 8, 256>>>(p_h, p_rows, p_csr, p_deg, p_mean);
    k_gemm<<<32768 / 128, 256>>>(p_mean, p_h, w3l, w3r, b3, p_h2);
    k_score<<<32768 / 8, 256>>>(p_h2, pw3, p_score);
    k_pool<<<64, 1024>>>(p_h2, p_score, p_h, p_kept, p_newidx, 512, 256);
    k_readout<<<64, 1024>>>(p_h, p_z, 256);

    // ===== head =====
    k_mlp<<<64, 128>>>(p_z, l1w, l1b, l2w, l2b, l3w, l3b, out);
}

// round 10
// speedup vs baseline: 1.0757x; 1.0757x over previous
#include <cuda_runtime.h>
#include <cuda_bf16.h>
#include <stdint.h>
#include <math.h>

#define NF 128
#define NB 64
#define NODES1 131072
#define EMAX 2097152

// ---------------- scratch (static device globals; no allocation) ----------------
__device__ float g_h[NODES1 * NF];      // ping (pooled h)
__device__ float g_h2[NODES1 * NF];     // pong (gemm output)
__device__ float g_mean[NODES1 * NF];   // aggregated means
__device__ int   g_esrc[EMAX];
__device__ int   g_edst[EMAX];
__device__ int   g_esrc2[EMAX];
__device__ int   g_edst2[EMAX];
__device__ int   g_csr[EMAX];
__device__ int   g_deg[NODES1];
__device__ int   g_rows[NODES1];
__device__ int   g_curs[NODES1];
__device__ int   g_kept[NODES1];
__device__ int   g_newidx[NODES1];
__device__ float g_score[NODES1];
__device__ float g_z[NB * 256];
__device__ int   g_cnt[4];
__device__ __nv_bfloat16 g_wthi[3 * 128 * 256];  // transposed [N=128,K=256] hi parts
__device__ __nv_bfloat16 g_wtlo[3 * 128 * 256];  // lo parts

// ---------------- mma helpers (sm_103 baseline tensor core path) ----------------
__device__ __forceinline__ uint32_t smem_to_u32(const void* p) {
    uint32_t a;
    asm("{ .reg .u64 t; cvta.to.shared.u64 t, %1; cvt.u32.u64 %0, t; }" : "=r"(a) : "l"(p));
    return a;
}
__device__ __forceinline__ void ldsm_x4(uint32_t r[4], uint32_t addr) {
    asm volatile("ldmatrix.sync.aligned.m8n8.x4.shared.b16 {%0,%1,%2,%3}, [%4];"
                 : "=r"(r[0]), "=r"(r[1]), "=r"(r[2]), "=r"(r[3]) : "r"(addr));
}
__device__ __forceinline__ void mma_bf16(float* c, const uint32_t* a, const uint32_t* b) {
    asm volatile("mma.sync.aligned.m16n8k16.row.col.f32.bf16.bf16.f32 "
                 "{%0,%1,%2,%3}, {%4,%5,%6,%7}, {%8,%9}, {%0,%1,%2,%3};"
                 : "+f"(c[0]), "+f"(c[1]), "+f"(c[2]), "+f"(c[3])
                 : "r"(a[0]), "r"(a[1]), "r"(a[2]), "r"(a[3]), "r"(b[0]), "r"(b[1]));
}

// SMEM tile geometry: [128 rows][256 k] bf16, padded pitch 264 bf16 (528 B)
#define PITCHB   528
#define ATILE    67584            // 128 * 528
#define OFF_AHI  0
#define OFF_ALO  67584
#define OFF_W    135168
#define OFF_BIAS 202752
#define OFF_PW   203264
#define OFF_SC   203776
#define OFF_INV  204288
#define GSMEM    204304

// ---------------- small utility kernels ----------------
__global__ void k_init() { g_cnt[0] = EMAX; g_cnt[1] = 0; g_cnt[2] = 0; }
__global__ void k_zero_i(int* p, int n) {
    int i = blockIdx.x * blockDim.x + threadIdx.x;
    if (i < n) p[i] = 0;
}
__global__ void k_zero_f(float* p, int n) {
    int i = blockIdx.x * blockDim.x + threadIdx.x;
    if (i < n) p[i] = 0.f;
}

// weight transpose + bf16 hi/lo split: Wt[n][k] = (k<128 ? Wl[k][n] : Wr[k-128][n])
__global__ void k_wconv(const float* __restrict__ wl, const float* __restrict__ wr,
                        __nv_bfloat16* __restrict__ whi, __nv_bfloat16* __restrict__ wlo) {
    int idx = blockIdx.x * blockDim.x + threadIdx.x;  // 32768
    int n = idx >> 8, k = idx & 255;
    float w = (k < 128) ? wl[k * 128 + n] : wr[(k - 128) * 128 + n];
    __nv_bfloat16 hi = __float2bfloat16_rn(w);
    __nv_bfloat16 lo = __float2bfloat16_rn(w - __bfloat162float(hi));
    whi[idx] = hi;
    wlo[idx] = lo;
}

// ---------------- CSR build ----------------
__global__ void k_hist(const int* __restrict__ dst, const int* __restrict__ pcnt,
                       int* __restrict__ deg) {
    int En = *pcnt;
    int stride = gridDim.x * blockDim.x;
    for (int e = blockIdx.x * blockDim.x + threadIdx.x; e < En; e += stride)
        atomicAdd(&deg[dst[e]], 1);
}
__global__ void k_scatter(const int* __restrict__ src, const int* __restrict__ dst,
                          const int* __restrict__ pcnt, const int* __restrict__ rows,
                          int* __restrict__ curs, int* __restrict__ csr) {
    int En = *pcnt;
    int stride = gridDim.x * blockDim.x;
    for (int e = blockIdx.x * blockDim.x + threadIdx.x; e < En; e += stride) {
        int d = dst[e];
        int p = atomicAdd(&curs[d], 1);
        csr[rows[d] + p] = src[e];
    }
}
__global__ void k_scan(const int* __restrict__ in, int* __restrict__ out, int n) {
    __shared__ int swarp[32];
    __shared__ int scarry;
    int tid = threadIdx.x, lane = tid & 31, w = tid >> 5;
    if (tid == 0) scarry = 0;
    __syncthreads();
    for (int base = 0; base < n; base += 8192) {
        int idx = base + tid * 8;
        int4 a = *(const int4*)(in + idx);
        int4 b = *(const int4*)(in + idx + 4);
        int p0 = 0;
        int p1 = p0 + a.x, p2 = p1 + a.y, p3 = p2 + a.z, p4 = p3 + a.w;
        int p5 = p4 + b.x, p6 = p5 + b.y, p7 = p6 + b.z;
        int s = p7 + b.w;
        int incl = s;
        #pragma unroll
        for (int o = 1; o < 32; o <<= 1) {
            int t = __shfl_up_sync(0xffffffffu, incl, o);
            if (lane >= o) incl += t;
        }
        if (lane == 31) swarp[w] = incl;
        __syncthreads();
        if (w == 0) {
            int ws = swarp[lane];
            int wincl = ws;
            #pragma unroll
            for (int o = 1; o < 32; o <<= 1) {
                int t = __shfl_up_sync(0xffffffffu, wincl, o);
                if (lane >= o) wincl += t;
            }
            swarp[lane] = wincl - ws;
        }
        __syncthreads();
        int off = scarry + swarp[w] + (incl - s);
        int4 o1; o1.x = off + p0; o1.y = off + p1; o1.z = off + p2; o1.w = off + p3;
        int4 o2; o2.x = off + p4; o2.y = off + p5; o2.z = off + p6; o2.w = off + p7;
        *(int4*)(out + idx) = o1;
        *(int4*)(out + idx + 4) = o2;
        __syncthreads();
        if (tid == 1023) scarry = off + s;
        __syncthreads();
    }
}

// ---------------- neighbor mean aggregation: one warp per node ----------------
__global__ void k_aggregate(const float* __restrict__ x, const int* __restrict__ rows,
                            const int* __restrict__ csr, const int* __restrict__ deg,
                            float* __restrict__ mb) {
    int node = blockIdx.x * 8 + (threadIdx.x >> 5);
    int lane = threadIdx.x & 31;
    int r0 = rows[node];
    int d = deg[node];
    float ax = 0.f, ay = 0.f, az = 0.f, aw = 0.f;
    int j = 0;
    for (; j + 4 <= d; j += 4) {
        int s0 = csr[r0 + j], s1 = csr[r0 + j + 1], s2 = csr[r0 + j + 2], s3 = csr[r0 + j + 3];
        float4 v0 = *(const float4*)(x + (size_t)s0 * NF + lane * 4);
        float4 v1 = *(const float4*)(x + (size_t)s1 * NF + lane * 4);
        float4 v2 = *(const float4*)(x + (size_t)s2 * NF + lane * 4);
        float4 v3 = *(const float4*)(x + (size_t)s3 * NF + lane * 4);
        ax += v0.x + v1.x + v2.x + v3.x;
        ay += v0.y + v1.y + v2.y + v3.y;
        az += v0.z + v1.z + v2.z + v3.z;
        aw += v0.w + v1.w + v2.w + v3.w;
    }
    for (; j < d; j++) {
        int s = csr[r0 + j];
        float4 v = *(const float4*)(x + (size_t)s * NF + lane * 4);
        ax += v.x; ay += v.y; az += v.z; aw += v.w;
    }
    float inv = 1.f / (float)(d > 0 ? d : 1);
    float4 o; o.x = ax * inv; o.y = ay * inv; o.z = az * inv; o.w = aw * inv;
    *(float4*)(mb + (size_t)node * NF + lane * 4) = o;
}

// ---------------- warp-mma GEMM: h = relu([mean|x] @ Wt^T + b), fused score ----------------
// A = [mean|x] 128 rows x K=256 per CTA; W [N=128, K=256]; bf16 split 3-term.
// Warps: 4 along M (32 rows) x 2 along N (64 cols). C in registers across passes.
__device__ __forceinline__ void gemm_pass(uint32_t aBase, uint32_t wBase,
                                          int wm, int wn, int lane, float cc[16][4]) {
    int arow = wm + (lane & 15);
    int acol = (lane >> 4) << 3;
    uint32_t aaddr = aBase + (uint32_t)arow * PITCHB + (uint32_t)acol * 2;
    int brow = (lane & 7) + ((lane >> 4) << 3);
    int bcol = ((lane >> 3) & 1) << 3;
    uint32_t baddr = wBase + (uint32_t)(wn + brow) * PITCHB + (uint32_t)bcol * 2;
    #pragma unroll
    for (int ks = 0; ks < 16; ks++) {
        uint32_t a0[4], a1[4], b[4][4];
        ldsm_x4(a0, aaddr + ks * 32);
        ldsm_x4(a1, aaddr + 16 * PITCHB + ks * 32);
        #pragma unroll
        for (int ng = 0; ng < 4; ng++)
            ldsm_x4(b[ng], baddr + ng * 16 * PITCHB + ks * 32);
        #pragma unroll
        for (int nt = 0; nt < 8; nt++) {
            mma_bf16(cc[nt],     a0, &b[nt >> 1][(nt & 1) * 2]);
            mma_bf16(cc[8 + nt], a1, &b[nt >> 1][(nt & 1) * 2]);
        }
    }
}

__global__ void __launch_bounds__(256) k_gemm_tc(
    const float* __restrict__ A, const float* __restrict__ X,
    const __nv_bfloat16* __restrict__ wthi, const __nv_bfloat16* __restrict__ wtlo,
    const float* __restrict__ bias, const float* __restrict__ pw,
    float* __restrict__ out, float* __restrict__ score) {
    extern __shared__ char smem[];
    uint32_t sb = smem_to_u32(smem);
    int tid = threadIdx.x, wid = tid >> 5, lane = tid & 31;
    int r0 = blockIdx.x * 128;

    float* sbias = (float*)(smem + OFF_BIAS);
    float* spw   = (float*)(smem + OFF_PW);
    float* ssc   = (float*)(smem + OFF_SC);
    if (tid < 128) {
        sbias[tid] = bias[tid];
        spw[tid] = pw[tid];
        ssc[tid] = 0.f;
    }
    __syncthreads();
    if (tid == 0) {
        float s = 0.f;
        for (int i = 0; i < 128; i++) s += spw[i] * spw[i];
        *(float*)(smem + OFF_INV) = rsqrtf(s);
    }

    // ---- load A (mean -> k 0..127, x -> k 128..255), split hi/lo, padded layout ----
    for (int c = tid; c < 4096; c += 256) {
        int row = c >> 5, col4 = (c & 31) << 2;
        float4 v = *(const float4*)(A + (size_t)(r0 + row) * 128 + col4);
        float4 u = *(const float4*)(X + (size_t)(r0 + row) * 128 + col4);
        #pragma unroll
        for (int half = 0; half < 2; half++) {
            float4 w = half ? u : v;
            __nv_bfloat16 hx = __float2bfloat16_rn(w.x), hy = __float2bfloat16_rn(w.y);
            __nv_bfloat16 hz = __float2bfloat16_rn(w.z), hw = __float2bfloat16_rn(w.w);
            __nv_bfloat16 lx = __float2bfloat16_rn(w.x - __bfloat162float(hx));
            __nv_bfloat16 ly = __float2bfloat16_rn(w.y - __bfloat162float(hy));
            __nv_bfloat16 lz = __float2bfloat16_rn(w.z - __bfloat162float(hz));
            __nv_bfloat16 lw = __float2bfloat16_rn(w.w - __bfloat162float(hw));
            __nv_bfloat162 h01 = __halves2bfloat162(hx, hy), h23 = __halves2bfloat162(hz, hw);
            __nv_bfloat162 l01 = __halves2bfloat162(lx, ly), l23 = __halves2bfloat162(lz, lw);
            uint32_t off = (uint32_t)row * PITCHB + (uint32_t)(half * 128 + col4) * 2;
            uint2 hv; hv.x = *(uint32_t*)&h01; hv.y = *(uint32_t*)&h23;
            uint2 lv; lv.x = *(uint32_t*)&l01; lv.y = *(uint32_t*)&l23;
            *(uint2*)(smem + OFF_AHI + off) = hv;
            *(uint2*)(smem + OFF_ALO + off) = lv;
        }
    }
    // ---- load W_hi [N=128][K=256] bf16 into padded tile ----
    for (int c = tid; c < 4096; c += 256) {
        int n = c >> 5, k8 = (c & 31) << 3;
        uint4 raw = *(const uint4*)(wthi + (size_t)n * 256 + k8);
        *(uint4*)(smem + OFF_W + (uint32_t)n * PITCHB + (uint32_t)k8 * 2) = raw;
    }
    __syncthreads();

    int wm = (wid & 3) * 32, wn = (wid >> 2) * 64;
    float cc[16][4];
    #pragma unroll
    for (int i = 0; i < 16; i++)
        #pragma unroll
        for (int j = 0; j < 4; j++) cc[i][j] = 0.f;

    gemm_pass(sb + OFF_AHI, sb + OFF_W, wm, wn, lane, cc);   // A_hi * W_hi
    gemm_pass(sb + OFF_ALO, sb + OFF_W, wm, wn, lane, cc);   // A_lo * W_hi
    __syncthreads();
    for (int c = tid; c < 4096; c += 256) {                  // swap in W_lo
        int n = c >> 5, k8 = (c & 31) << 3;
        uint4 raw = *(const uint4*)(wtlo + (size_t)n * 256 + k8);
        *(uint4*)(smem + OFF_W + (uint32_t)n * PITCHB + (uint32_t)k8 * 2) = raw;
    }
    __syncthreads();
    gemm_pass(sb + OFF_AHI, sb + OFF_W, wm, wn, lane, cc);   // A_hi * W_lo

    // ---- epilogue: bias + relu + store + fused score partial dots ----
    int g = lane >> 2, tig = lane & 3;
    float p[4] = {0.f, 0.f, 0.f, 0.f};  // rows: wm+g, wm+8+g, wm+16+g, wm+24+g
    #pragma unroll
    for (int mt = 0; mt < 2; mt++) {
        #pragma unroll
        for (int nt = 0; nt < 8; nt++) {
            float* cf = cc[mt * 8 + nt];
            int col0 = wn + nt * 8 + tig * 2;
            float pw0 = spw[col0], pw1 = spw[col0 + 1];
            float b0 = sbias[col0], b1 = sbias[col0 + 1];
            float o0 = fmaxf(cf[0] + b0, 0.f), o1 = fmaxf(cf[1] + b1, 0.f);
            float o2 = fmaxf(cf[2] + b0, 0.f), o3 = fmaxf(cf[3] + b1, 0.f);
            int rowA = r0 + wm + mt * 16 + g;
            float2 s0; s0.x = o0; s0.y = o1;
            float2 s1; s1.x = o2; s1.y = o3;
            *(float2*)(out + (size_t)rowA * 128 + col0) = s0;
            *(float2*)(out + (size_t)(rowA + 8) * 128 + col0) = s1;
            p[mt * 2 + 0] += o0 * pw0 + o1 * pw1;
            p[mt * 2 + 1] += o2 * pw0 + o3 * pw1;
        }
    }
    #pragma unroll
    for (int off = 1; off <= 2; off <<= 1) {
        #pragma unroll
        for (int i = 0; i < 4; i++) p[i] += __shfl_xor_sync(0xffffffffu, p[i], off);
    }
    if (tig == 0) {
        atomicAdd(&ssc[wm + g], p[0]);
        atomicAdd(&ssc[wm + 8 + g], p[1]);
        atomicAdd(&ssc[wm + 16 + g], p[2]);
        atomicAdd(&ssc[wm + 24 + g], p[3]);
    }
    __syncthreads();
    if (tid < 128) {
        float invn = *(const float*)(smem + OFF_INV);
        score[r0 + tid] = tanhf(ssc[tid] * invn);
    }
}

// ---------------- per-graph top-k pool (bitonic sort, reference tie-break) ----------------
__global__ void k_pool(const float* __restrict__ h, const float* __restrict__ score,
                       float* __restrict__ hout, int* __restrict__ kept,
                       int* __restrict__ newidx, int n_per, int k) {
    __shared__ unsigned long long s_key[2048];
    int g = blockIdx.x;
    int tid = threadIdx.x;
    int bd = blockDim.x;
    int base = g * n_per;
    for (int i = tid; i < n_per; i += bd) {
        float s = score[base + i];
        unsigned u = __float_as_uint(s);
        unsigned au = (u & 0x80000000u) ? ~u : (u | 0x80000000u);
        unsigned du = ~au;
        s_key[i] = ((unsigned long long)du << 32) | (unsigned)i;
        kept[base + i] = 0;
    }
    for (int size = 2; size <= n_per; size <<= 1) {
        for (int stride = size >> 1; stride > 0; stride >>= 1) {
            __syncthreads();
            int half = n_per >> 1;
            for (int t = tid; t < half; t += bd) {
                int i = 2 * t - (t & (stride - 1));
                int j = i + stride;
                unsigned long long a = s_key[i], c = s_key[j];
                bool up = ((i & size) == 0);
                if ((a > c) == up) { s_key[i] = c; s_key[j] = a; }
            }
        }
    }
    __syncthreads();
    for (int t = tid; t < k; t += bd) {
        int li = (int)(s_key[t] & 0xffffffffull);
        kept[base + li] = 1;
        newidx[base + li] = g * k + t;
    }
    int w = tid >> 5, lane = tid & 31, nw = bd >> 5;
    for (int t = w; t < k; t += nw) {
        int li = (int)(s_key[t] & 0xffffffffull);
        int v = base + li;
        float sc = score[v];
        float4 val = *(const float4*)(h + (size_t)v * NF + lane * 4);
        float4 o; o.x = val.x * sc; o.y = val.y * sc; o.z = val.z * sc; o.w = val.w * sc;
        *(float4*)(hout + (size_t)(g * k + t) * NF + lane * 4) = o;
    }
}

// ---------------- drop masked edges + relabel ----------------
__global__ void k_compact(const int* __restrict__ src, const int* __restrict__ dst,
                          const int* __restrict__ pcnt, const int* __restrict__ kept,
                          const int* __restrict__ newidx,
                          int* __restrict__ osrc, int* __restrict__ odst,
                          int* __restrict__ ocnt) {
    int En = *pcnt;
    int lane = threadIdx.x & 31;
    int stride = gridDim.x * blockDim.x;
    int base = blockIdx.x * blockDim.x + (threadIdx.x & ~31);
    for (int b = base; b < En; b += stride) {
        int e = b + lane;
        bool keep = false;
        int ns = 0, nd = 0;
        if (e < En) {
            int s = src[e], d2 = dst[e];
            if (kept[s] && kept[d2]) { keep = true; ns = newidx[s]; nd = newidx[d2]; }
        }
        unsigned m = __ballot_sync(0xffffffffu, keep);
        int cnt = __popc(m);
        int pos = 0;
        if (lane == 0 && cnt) pos = atomicAdd(ocnt, cnt);
        pos = __shfl_sync(0xffffffffu, pos, 0);
        if (keep) {
            int off = __popc(m & ((1u << lane) - 1u));
            osrc[pos + off] = ns;
            odst[pos + off] = nd;
        }
    }
}

// ---------------- readout ----------------
__global__ void k_readout(const float* __restrict__ h, float* __restrict__ z, int n_per) {
    __shared__ float smx[8][128];
    __shared__ float ssm[8][128];
    int g = blockIdx.x;
    int tid = threadIdx.x;
    int f = tid & 127, grp = tid >> 7;
    float mx = -3.402823466e38f, sm = 0.f;
    for (int r = grp; r < n_per; r += 8) {
        float v = h[(size_t)(g * n_per + r) * NF + f];
        mx = fmaxf(mx, v);
        sm += v;
    }
    smx[grp][f] = mx;
    ssm[grp][f] = sm;
    __syncthreads();
    if (grp == 0) {
        for (int j = 1; j < 8; j++) { mx = fmaxf(mx, smx[j][f]); sm += ssm[j][f]; }
        z[g * 256 + f] += mx;
        z[g * 256 + 128 + f] += sm / (float)n_per;
    }
}

// ---------------- final MLP + log_softmax ----------------
__global__ void k_mlp(const float* __restrict__ z,
                      const float* __restrict__ w1, const float* __restrict__ b1,
                      const float* __restrict__ w2, const float* __restrict__ b2,
                      const float* __restrict__ w3, const float* __restrict__ b3,
                      float* __restrict__ out) {
    __shared__ float zin[256];
    __shared__ float h1[128];
    __shared__ float h2[64];
    __shared__ float z2[2];
    int g = blockIdx.x, tid = threadIdx.x;
    zin[tid] = z[g * 256 + tid];
    zin[tid + 128] = z[g * 256 + 128 + tid];
    __syncthreads();
    float a = b1[tid];
    for (int k2 = 0; k2 < 256; k2++) a += zin[k2] * w1[k2 * 128 + tid];
    h1[tid] = fmaxf(a, 0.f);
    __syncthreads();
    if (tid < 64) {
        float a2 = b2[tid];
        for (int k2 = 0; k2 < 128; k2++) a2 += h1[k2] * w2[k2 * 64 + tid];
        h2[tid] = fmaxf(a2, 0.f);
    }
    __syncthreads();
    if (tid < 2) {
        float a3 = b3[tid];
        for (int k2 = 0; k2 < 64; k2++) a3 += h2[k2] * w3[k2 * 2 + tid];
        z2[tid] = a3;
    }
    __syncthreads();
    if (tid < 2) {
        float m = fmaxf(z2[0], z2[1]);
        float lse = m + logf(expf(z2[0] - m) + expf(z2[1] - m));
        out[g * 2 + tid] = z2[tid] - lse;
    }
}

// ---------------- host ----------------
extern "C" void kernel_launch(void* const* d_in, const int* in_sizes, int n_in,
                              void* d_out, int out_size) {
    const float* x   = (const float*)d_in[0];
    const int*   src = (const int*)d_in[1];
    const int*   dst = (const int*)d_in[2];
    const float* w1l = (const float*)d_in[3];
    const float* b1  = (const float*)d_in[4];
    const float* w1r = (const float*)d_in[5];
    const float* pw1 = (const float*)d_in[6];
    const float* w2l = (const float*)d_in[7];
    const float* b2  = (const float*)d_in[8];
    const float* w2r = (const float*)d_in[9];
    const float* pw2 = (const float*)d_in[10];
    const float* w3l = (const float*)d_in[11];
    const float* b3  = (const float*)d_in[12];
    const float* w3r = (const float*)d_in[13];
    const float* pw3 = (const float*)d_in[14];
    const float* l1w = (const float*)d_in[15];
    const float* l1b = (const float*)d_in[16];
    const float* l2w = (const float*)d_in[17];
    const float* l2b = (const float*)d_in[18];
    const float* l3w = (const float*)d_in[19];
    const float* l3b = (const float*)d_in[20];
    float* out = (float*)d_out;

    float *p_h, *p_h2, *p_mean, *p_score, *p_z;
    int *p_esrc, *p_edst, *p_esrc2, *p_edst2, *p_csr, *p_deg, *p_rows, *p_curs,
        *p_kept, *p_newidx, *p_cnt;
    __nv_bfloat16 *p_wthi, *p_wtlo;
    cudaGetSymbolAddress((void**)&p_h, g_h);
    cudaGetSymbolAddress((void**)&p_h2, g_h2);
    cudaGetSymbolAddress((void**)&p_mean, g_mean);
    cudaGetSymbolAddress((void**)&p_score, g_score);
    cudaGetSymbolAddress((void**)&p_z, g_z);
    cudaGetSymbolAddress((void**)&p_esrc, g_esrc);
    cudaGetSymbolAddress((void**)&p_edst, g_edst);
    cudaGetSymbolAddress((void**)&p_esrc2, g_esrc2);
    cudaGetSymbolAddress((void**)&p_edst2, g_edst2);
    cudaGetSymbolAddress((void**)&p_csr, g_csr);
    cudaGetSymbolAddress((void**)&p_deg, g_deg);
    cudaGetSymbolAddress((void**)&p_rows, g_rows);
    cudaGetSymbolAddress((void**)&p_curs, g_curs);
    cudaGetSymbolAddress((void**)&p_kept, g_kept);
    cudaGetSymbolAddress((void**)&p_newidx, g_newidx);
    cudaGetSymbolAddress((void**)&p_cnt, g_cnt);
    cudaGetSymbolAddress((void**)&p_wthi, g_wthi);
    cudaGetSymbolAddress((void**)&p_wtlo, g_wtlo);

    cudaFuncSetAttribute(k_gemm_tc, cudaFuncAttributeMaxDynamicSharedMemorySize, GSMEM);

    k_init<<<1, 1>>>();
    k_zero_f<<<(NB * 256 + 255) / 256, 256>>>(p_z, NB * 256);
    k_wconv<<<128, 256>>>(w1l, w1r, p_wthi, p_wtlo);
    k_wconv<<<128, 256>>>(w2l, w2r, p_wthi + 32768, p_wtlo + 32768);
    k_wconv<<<128, 256>>>(w3l, w3r, p_wthi + 65536, p_wtlo + 65536);

    // ===== layer 1 =====
    k_zero_i<<<(131072 + 255) / 256, 256>>>(p_deg, 131072);
    k_zero_i<<<(131072 + 255) / 256, 256>>>(p_curs, 131072);
    k_hist<<<2048, 256>>>(dst, p_cnt + 0, p_deg);
    k_scan<<<1, 1024>>>(p_deg, p_rows, 131072);
    k_scatter<<<2048, 256>>>(src, dst, p_cnt + 0, p_rows, p_curs, p_csr);
    k_aggregate<<<131072 / 8, 256>>>(x, p_rows, p_csr, p_deg, p_mean);
    k_gemm_tc<<<131072 / 128, 256, GSMEM>>>(p_mean, x, p_wthi, p_wtlo, b1, pw1, p_h2, p_score);
    k_pool<<<64, 1024>>>(p_h2, p_score, p_h, p_kept, p_newidx, 2048, 1024);
    k_compact<<<2048, 256>>>(src, dst, p_cnt + 0, p_kept, p_newidx, p_esrc, p_edst, p_cnt + 1);
    k_readout<<<64, 1024>>>(p_h, p_z, 1024);

    // ===== layer 2 =====
    k_zero_i<<<(65536 + 255) / 256, 256>>>(p_deg, 65536);
    k_zero_i<<<(65536 + 255) / 256, 256>>>(p_curs, 65536);
    k_hist<<<2048, 256>>>(p_edst, p_cnt + 1, p_deg);
    k_scan<<<1, 1024>>>(p_deg, p_rows, 65536);
    k_scatter<<<2048, 256>>>(p_esrc, p_edst, p_cnt + 1, p_rows, p_curs, p_csr);
    k_aggregate<<<65536 / 8, 256>>>(p_h, p_rows, p_csr, p_deg, p_mean);
    k_gemm_tc<<<65536 / 128, 256, GSMEM>>>(p_mean, p_h, p_wthi + 32768, p_wtlo + 32768, b2, pw2, p_h2, p_score);
    k_pool<<<64, 1024>>>(p_h2, p_score, p_h, p_kept, p_newidx, 1024, 512);
    k_compact<<<2048, 256>>>(p_esrc, p_edst, p_cnt + 1, p_kept, p_newidx, p_esrc2, p_edst2, p_cnt + 2);
    k_readout<<<64, 1024>>>(p_h, p_z, 512);

    // ===== layer 3 =====
    k_zero_i<<<(32768 + 255) / 256, 256>>>(p_deg, 32768);
    k_zero_i<<<(32768 + 255) / 256, 256>>>(p_curs, 32768);
    k_hist<<<2048, 256>>>(p_edst2, p_cnt + 2, p_deg);
    k_scan<<<1, 1024>>>(p_deg, p_rows, 32768);
    k_scatter<<<2048, 256>>>(p_esrc2, p_edst2, p_cnt + 2, p_rows, p_curs, p_csr);
    k_aggregate<<<32768 / 8, 256>>>(p_h, p_rows, p_csr, p_deg, p_mean);
    k_gemm_tc<<<32768 / 128, 256, GSMEM>>>(p_mean, p_h, p_wthi + 65536, p_wtlo + 65536, b3, pw3, p_h2, p_score);
    k_pool<<<64, 1024>>>(p_h2, p_score, p_h, p_kept, p_newidx, 512, 256);
    k_readout<<<64, 1024>>>(p_h, p_z, 256);

    // ===== head =====
    k_mlp<<<64, 128>>>(p_z, l1w, l1b, l2w, l2b, l3w, l3b, out);
}